// round 3
// baseline (speedup 1.0000x reference)
#include <cuda_runtime.h>
#include <math.h>
#include <stdint.h>

// ---------------------------------------------------------------------------
// KAN feedforward: two layers of  y = silu(x) @ Wbase + sum_g B_g(x) @ Wg
// Reformulated as GEMM:  y = F @ W  with F = [silu(x), B_0..B_7] per input dim
// Dims: N=4096 tokens, D=512, H=1024.  K1 = 512*9 = 4608, K2 = 1024*9 = 9216.
// ---------------------------------------------------------------------------

#define D_MODEL 512
#define HIDDEN  1024
#define NFEAT   9
#define NTOK    4096

// Scratch (static device globals; allocation inside kernel_launch is banned)
__device__ float g_W1[D_MODEL * NFEAT * HIDDEN];           // 18.9 MB  [4608][1024]
__device__ float g_W2[HIDDEN * NFEAT * D_MODEL];           // 18.9 MB  [9216][512]
__device__ float g_F [HIDDEN * NFEAT * NTOK];              // 151 MB   [K][N] k-major
__device__ float g_h [NTOK * HIDDEN];                      // 16 MB    [N][H]

// ---------------------------------------------------------------------------
// Spline helpers
// ---------------------------------------------------------------------------
// Reference grid: pts = arange(-3, 9, f32) * 0.4f - 1.0f  (12 knots, h = 0.4)
// Use explicit rn mul/add so nvcc cannot FMA-contract (must bit-match ref knots
// for the half-open interval comparisons).
__device__ __forceinline__ float knotf(int k) {
    return __fadd_rn(__fmul_rn((float)(k - 3), 0.4f), -1.0f);
}

// Compute the 9 features for a scalar x: f[0] = silu(x); f[1+g] = B_g(x).
__device__ __forceinline__ void kan_features(float x, float f[NFEAT]) {
    // silu
    float sig = 1.0f / (1.0f + expf(-x));
    f[0] = x * sig;
#pragma unroll
    for (int g = 0; g < 8; g++) f[1 + g] = 0.0f;

    // interval index j with t_j <= x < t_{j+1}; correct against exact fp32 knots
    float u = (x - knotf(0)) * 2.5f;
    int j = (int)floorf(u);
    if (j < -1) j = -1;
    if (j > 11) j = 11;
    if (x < knotf(j))            j -= 1;
    else if (x >= knotf(j + 1))  j += 1;
    if (j < 0 || j > 10) return;   // outside [t0, t11): all bases zero

    float s  = (x - knotf(j)) * 2.5f;   // local parameter in [0,1)
    float s2 = s * s, s3 = s2 * s;
    float om = 1.0f - s;
    float w0 = om * om * om * (1.0f / 6.0f);                      // g = j-3
    float w1 = (3.0f * s3 - 6.0f * s2 + 4.0f) * (1.0f / 6.0f);    // g = j-2
    float w2 = (-3.0f * s3 + 3.0f * s2 + 3.0f * s + 1.0f) * (1.0f / 6.0f); // g=j-1
    float w3 = s3 * (1.0f / 6.0f);                                // g = j
    float w[4] = {w0, w1, w2, w3};
    int g0 = j - 3;
#pragma unroll
    for (int r = 0; r < 4; r++) {
        int g = g0 + r;
        if (g >= 0 && g < 8) f[1 + g] = w[r];
    }
}

// ---------------------------------------------------------------------------
// Fold weights:  W[i*9 + 0][o] = scale_base[i][o]
//                W[i*9 + 1+g][o] = coef[i][o][g] * scale_sp[i][o]
// ---------------------------------------------------------------------------
__global__ void prep_weights(const float* __restrict__ coef,
                             const float* __restrict__ sbase,
                             const float* __restrict__ ssp,
                             float* __restrict__ W, int I, int O) {
    int idx = blockIdx.x * blockDim.x + threadIdx.x;   // over I*O
    if (idx >= I * O) return;
    int i = idx / O;
    int o = idx - i * O;
    size_t rowbase = (size_t)i * NFEAT * O + o;
    float sp = ssp[idx];
    W[rowbase] = sbase[idx];
    const float* c = coef + (size_t)idx * 8;
#pragma unroll
    for (int g = 0; g < 8; g++)
        W[rowbase + (size_t)(g + 1) * O] = c[g] * sp;
}

// ---------------------------------------------------------------------------
// Feature expansion with smem transpose: X[N][I] row-major -> F[k][N] k-major
// Block handles a 32(n) x 32(i) tile; threads (32, 8).
// ---------------------------------------------------------------------------
__global__ void build_features(const float* __restrict__ X,
                               float* __restrict__ F, int I, int N) {
    __shared__ float xs[32][33];
    int n0 = blockIdx.x * 32;
    int i0 = blockIdx.y * 32;
    int tx = threadIdx.x;   // 0..31
    int ty = threadIdx.y;   // 0..7

    // coalesced load: tx -> i
#pragma unroll
    for (int r = ty; r < 32; r += 8)
        xs[r][tx] = X[(size_t)(n0 + r) * I + i0 + tx];
    __syncthreads();

    // compute: tx -> n, loop over i
    for (int ii = ty; ii < 32; ii += 8) {
        float f[NFEAT];
        kan_features(xs[tx][ii], f);
        size_t kbase = (size_t)(i0 + ii) * NFEAT;
#pragma unroll
        for (int fi = 0; fi < NFEAT; fi++)
            F[(kbase + fi) * (size_t)N + n0 + tx] = f[fi];   // coalesced along n
    }
}

// ---------------------------------------------------------------------------
// FP32 register-tiled GEMM:  C[m][o] = sum_k A[k][m] * B[k][o]
// A is k-major [Ktot][LDA] (LDA = N), B is [Ktot][LDB], C is [M][LDB].
// 256 threads, BMxBN tile, TMxTN micro-tiles, double-buffered gmem loads.
// ---------------------------------------------------------------------------
template <int BM, int BN, int BK, int TM, int TN>
__global__ __launch_bounds__(256, 2)
void kan_gemm(const float* __restrict__ A, const float* __restrict__ B,
              float* __restrict__ C, int Ktot, int LDA, int LDB) {
    constexpr int AF4 = (BK * BM) / 1024;   // float4 loads per thread per stage
    constexpr int BF4 = (BK * BN) / 1024;
    static_assert(AF4 >= 1 && BF4 >= 1, "tile too small");

    __shared__ float As[BK][BM];
    __shared__ float Bs[BK][BN];

    const int tid = threadIdx.x;
    const int tx  = tid & 15;    // cols
    const int ty  = tid >> 4;    // rows
    const int m0  = blockIdx.y * BM;
    const int o0  = blockIdx.x * BN;

    float acc[TM][TN];
#pragma unroll
    for (int i = 0; i < TM; i++)
#pragma unroll
        for (int j = 0; j < TN; j++) acc[i][j] = 0.0f;

    float4 ra4[AF4], rb4[BF4];

    // ---- prologue: load stage 0 ----
#pragma unroll
    for (int it = 0; it < AF4; it++) {
        int fi = tid + it * 256;
        int kk = fi / (BM / 4);
        int mm = (fi - kk * (BM / 4)) * 4;
        ra4[it] = *reinterpret_cast<const float4*>(&A[(size_t)kk * LDA + m0 + mm]);
    }
#pragma unroll
    for (int it = 0; it < BF4; it++) {
        int fi = tid + it * 256;
        int kk = fi / (BN / 4);
        int oo = (fi - kk * (BN / 4)) * 4;
        rb4[it] = *reinterpret_cast<const float4*>(&B[(size_t)kk * LDB + o0 + oo]);
    }
#pragma unroll
    for (int it = 0; it < AF4; it++) {
        int fi = tid + it * 256;
        int kk = fi / (BM / 4);
        int mm = (fi - kk * (BM / 4)) * 4;
        *reinterpret_cast<float4*>(&As[kk][mm]) = ra4[it];
    }
#pragma unroll
    for (int it = 0; it < BF4; it++) {
        int fi = tid + it * 256;
        int kk = fi / (BN / 4);
        int oo = (fi - kk * (BN / 4)) * 4;
        *reinterpret_cast<float4*>(&Bs[kk][oo]) = rb4[it];
    }
    __syncthreads();

    for (int k0 = 0; k0 < Ktot; k0 += BK) {
        const bool notlast = (k0 + BK) < Ktot;
        if (notlast) {
            const float* Ap = A + (size_t)(k0 + BK) * LDA;
            const float* Bp = B + (size_t)(k0 + BK) * LDB;
#pragma unroll
            for (int it = 0; it < AF4; it++) {
                int fi = tid + it * 256;
                int kk = fi / (BM / 4);
                int mm = (fi - kk * (BM / 4)) * 4;
                ra4[it] = *reinterpret_cast<const float4*>(&Ap[(size_t)kk * LDA + m0 + mm]);
            }
#pragma unroll
            for (int it = 0; it < BF4; it++) {
                int fi = tid + it * 256;
                int kk = fi / (BN / 4);
                int oo = (fi - kk * (BN / 4)) * 4;
                rb4[it] = *reinterpret_cast<const float4*>(&Bp[(size_t)kk * LDB + o0 + oo]);
            }
        }
#pragma unroll
        for (int kk = 0; kk < BK; kk++) {
            float ra[TM], rb[TN];
#pragma unroll
            for (int i = 0; i < TM; i++) ra[i] = As[kk][ty * TM + i];
#pragma unroll
            for (int j = 0; j < TN; j++) rb[j] = Bs[kk][tx * TN + j];
#pragma unroll
            for (int i = 0; i < TM; i++)
#pragma unroll
                for (int j = 0; j < TN; j++)
                    acc[i][j] = fmaf(ra[i], rb[j], acc[i][j]);
        }
        __syncthreads();
        if (notlast) {
#pragma unroll
            for (int it = 0; it < AF4; it++) {
                int fi = tid + it * 256;
                int kk = fi / (BM / 4);
                int mm = (fi - kk * (BM / 4)) * 4;
                *reinterpret_cast<float4*>(&As[kk][mm]) = ra4[it];
            }
#pragma unroll
            for (int it = 0; it < BF4; it++) {
                int fi = tid + it * 256;
                int kk = fi / (BN / 4);
                int oo = (fi - kk * (BN / 4)) * 4;
                *reinterpret_cast<float4*>(&Bs[kk][oo]) = rb4[it];
            }
            __syncthreads();
        }
    }

    // ---- epilogue: coalesced float4 stores ----
#pragma unroll
    for (int i = 0; i < TM; i++) {
        float* crow = &C[(size_t)(m0 + ty * TM + i) * LDB + o0 + tx * TN];
#pragma unroll
        for (int j = 0; j < TN; j += 4) {
            float4 v = make_float4(acc[i][j], acc[i][j + 1], acc[i][j + 2], acc[i][j + 3]);
            *reinterpret_cast<float4*>(&crow[j]) = v;
        }
    }
}

// ---------------------------------------------------------------------------
// Launch
// ---------------------------------------------------------------------------
extern "C" void kernel_launch(void* const* d_in, const int* in_sizes, int n_in,
                              void* d_out, int out_size) {
    const float* x   = (const float*)d_in[0];  // [N, 512]
    const float* c1  = (const float*)d_in[1];  // [512, 1024, 8]
    const float* sb1 = (const float*)d_in[2];  // [512, 1024]
    const float* sp1 = (const float*)d_in[3];  // [512, 1024]
    const float* c2  = (const float*)d_in[4];  // [1024, 512, 8]
    const float* sb2 = (const float*)d_in[5];  // [1024, 512]
    const float* sp2 = (const float*)d_in[6];  // [1024, 512]
    float* out = (float*)d_out;                // [N, 512]

    const int D = D_MODEL, H = HIDDEN;
    const int N = in_sizes[0] / D;             // 4096

    void *pW1, *pW2, *pF, *pH;
    cudaGetSymbolAddress(&pW1, g_W1);
    cudaGetSymbolAddress(&pW2, g_W2);
    cudaGetSymbolAddress(&pF,  g_F);
    cudaGetSymbolAddress(&pH,  g_h);
    float* W1 = (float*)pW1;
    float* W2 = (float*)pW2;
    float* F  = (float*)pF;
    float* hb = (float*)pH;

    // Fold weights (both layers)
    prep_weights<<<(D * H + 255) / 256, 256>>>(c1, sb1, sp1, W1, D, H);
    prep_weights<<<(H * D + 255) / 256, 256>>>(c2, sb2, sp2, W2, H, D);

    // Layer 1: features + GEMM (K = 4608, O = 1024)
    build_features<<<dim3(N / 32, D / 32), dim3(32, 8)>>>(x, F, D, N);
    kan_gemm<128, 128, 16, 8, 8>
        <<<dim3(H / 128, N / 128), 256>>>(F, W1, hb, D * NFEAT, N, H);

    // Layer 2: features + GEMM (K = 9216, O = 512); BN=64 -> 256 CTAs
    build_features<<<dim3(N / 32, H / 32), dim3(32, 8)>>>(hb, F, H, N);
    kan_gemm<128, 64, 16, 8, 4>
        <<<dim3(D / 64, N / 128), 256>>>(F, W2, out, H * NFEAT, N, D);
}

// round 5
// speedup vs baseline: 1.7910x; 1.7910x over previous
#include <cuda_runtime.h>
#include <cuda_bf16.h>
#include <math.h>
#include <stdint.h>

// ---------------------------------------------------------------------------
// KAN feedforward via mma.sync bf16 (sm_80 PTX subset -> legal at compute_103)
// with 3-term precision split:
//   y = F @ W^T,  A' = [Fhi | Fhi | Flo],  B' = [Whi | Wlo | Whi]
//   error = missing Alo*Blo term (~1e-5 rel)
// Dims: Ntok=4096, D=512, H=1024.  Keff1=13824, Keff2=27648.
// ---------------------------------------------------------------------------

#define D_MODEL 512
#define HIDDEN  1024
#define NFEAT   9
#define NTOK    4096
#define KEFF1   (D_MODEL * NFEAT * 3)   // 13824
#define KEFF2   (HIDDEN  * NFEAT * 3)   // 27648

__device__ __nv_bfloat16 g_F  [(size_t)NTOK * KEFF2];     // 226 MB (per-layer reuse)
__device__ __nv_bfloat16 g_W1 [(size_t)HIDDEN * KEFF1];   // 28.3 MB
__device__ __nv_bfloat16 g_W2 [(size_t)D_MODEL * KEFF2];  // 28.3 MB
__device__ float         g_h  [(size_t)NTOK * HIDDEN];    // 16 MB

// ---------------------------------------------------------------------------
// Helpers
// ---------------------------------------------------------------------------
__device__ __forceinline__ uint32_t smem_u32(const void* p) {
    uint32_t a;
    asm("{ .reg .u64 t; cvta.to.shared.u64 t, %1; cvt.u32.u64 %0, t; }"
        : "=r"(a) : "l"(p));
    return a;
}

// SW128-style swizzle for 128B rows (8 x 16B units per row, 1024B atoms).
// base must be 1024B aligned.
__device__ __forceinline__ uint32_t lds_addr(uint32_t base, int row, int col16) {
    return base + row * 128 + ((col16 ^ (row & 7)) << 4);
}

#define CP_ASYNC16(sm, gm)                                                    \
    asm volatile("cp.async.cg.shared.global [%0], [%1], 16;"                  \
                 :: "r"(sm), "l"(gm) : "memory")
#define CP_COMMIT()  asm volatile("cp.async.commit_group;" ::: "memory")
#define CP_WAIT1()   asm volatile("cp.async.wait_group 1;" ::: "memory")

__device__ __forceinline__ void ldsm_x4(uint32_t r[4], uint32_t addr) {
    asm volatile("ldmatrix.sync.aligned.m8n8.x4.shared.b16 {%0,%1,%2,%3}, [%4];"
                 : "=r"(r[0]), "=r"(r[1]), "=r"(r[2]), "=r"(r[3]) : "r"(addr));
}

__device__ __forceinline__ void mma16816(float c[4], const uint32_t a[4],
                                         const uint32_t b[2]) {
    asm volatile(
        "mma.sync.aligned.m16n8k16.row.col.f32.bf16.bf16.f32 "
        "{%0,%1,%2,%3}, {%4,%5,%6,%7}, {%8,%9}, {%0,%1,%2,%3};"
        : "+f"(c[0]), "+f"(c[1]), "+f"(c[2]), "+f"(c[3])
        : "r"(a[0]), "r"(a[1]), "r"(a[2]), "r"(a[3]), "r"(b[0]), "r"(b[1]));
}

// ---------------------------------------------------------------------------
// Spline features (validated in R3: rel_err 3.1e-6 with fp32 GEMM)
// ---------------------------------------------------------------------------
__device__ __forceinline__ float knotf(int k) {
    return __fadd_rn(__fmul_rn((float)(k - 3), 0.4f), -1.0f);
}

__device__ __forceinline__ void kan_features(float x, float f[NFEAT]) {
    float sig = 1.0f / (1.0f + expf(-x));
    f[0] = x * sig;
#pragma unroll
    for (int g = 0; g < 8; g++) f[1 + g] = 0.0f;

    float u = (x - knotf(0)) * 2.5f;
    if (u > 16.0f) u = 16.0f;
    if (u < -16.0f) u = -16.0f;
    int j = (int)floorf(u);
    if (j < -1) j = -1;
    if (j > 11) j = 11;
    if (x < knotf(j))            j -= 1;
    else if (x >= knotf(j + 1))  j += 1;
    if (j < 0 || j > 10) return;

    float s  = (x - knotf(j)) * 2.5f;
    float s2 = s * s, s3 = s2 * s;
    float om = 1.0f - s;
    float w0 = om * om * om * (1.0f / 6.0f);
    float w1 = (3.0f * s3 - 6.0f * s2 + 4.0f) * (1.0f / 6.0f);
    float w2 = (-3.0f * s3 + 3.0f * s2 + 3.0f * s + 1.0f) * (1.0f / 6.0f);
    float w3 = s3 * (1.0f / 6.0f);
    float w[4] = {w0, w1, w2, w3};
    int g0 = j - 3;
#pragma unroll
    for (int r = 0; r < 4; r++) {
        int g = g0 + r;
        if (g >= 0 && g < 8) f[1 + g] = w[r];
    }
}

__device__ __forceinline__ void split_store(__nv_bfloat16* hi0, __nv_bfloat16* hi1,
                                            __nv_bfloat16* lo, float v) {
    __nv_bfloat16 h = __float2bfloat16(v);
    __nv_bfloat16 l = __float2bfloat16(v - __bfloat162float(h));
    *hi0 = h; *hi1 = h; *lo = l;
}

// ---------------------------------------------------------------------------
// Weight fold + quantize:  Wq[o][3K] = [Whi | Wlo | Whi],  K = I*9
// ---------------------------------------------------------------------------
__global__ void prep_weights_q(const float* __restrict__ coef,
                               const float* __restrict__ sbase,
                               const float* __restrict__ ssp,
                               __nv_bfloat16* __restrict__ Wq, int I, int O) {
    int idx = blockIdx.x * blockDim.x + threadIdx.x;
    if (idx >= I * O) return;
    int o = idx / I;
    int i = idx - o * I;
    int K = I * NFEAT;
    size_t io = (size_t)i * O + o;
    float sp = ssp[io];
    float w[NFEAT];
    w[0] = sbase[io];
    const float* c = coef + io * 8;
#pragma unroll
    for (int g = 0; g < 8; g++) w[1 + g] = c[g] * sp;

    size_t base = (size_t)o * 3 * K + (size_t)i * NFEAT;
#pragma unroll
    for (int fi = 0; fi < NFEAT; fi++)
        split_store(&Wq[base + fi], &Wq[base + 2 * (size_t)K + fi],
                    &Wq[base + (size_t)K + fi], w[fi]);   // [hi | lo | hi]
}

// ---------------------------------------------------------------------------
// Feature expand + quantize:  Fq[n][3K] = [Fhi | Fhi | Flo]
// ---------------------------------------------------------------------------
__global__ void build_features_q(const float* __restrict__ X,
                                 __nv_bfloat16* __restrict__ Fq, int I, int N) {
    int idx = blockIdx.x * blockDim.x + threadIdx.x;
    if (idx >= N * I) return;
    int n = idx / I;
    int i = idx - n * I;
    int K = I * NFEAT;
    float f[NFEAT];
    kan_features(X[idx], f);
    size_t base = (size_t)n * 3 * K + (size_t)i * NFEAT;
#pragma unroll
    for (int fi = 0; fi < NFEAT; fi++)
        split_store(&Fq[base + fi], &Fq[base + (size_t)K + fi],
                    &Fq[base + 2 * (size_t)K + fi], f[fi]);  // [hi | hi | lo]
}

// ---------------------------------------------------------------------------
// mma.sync bf16 GEMM:  C[m][o] = sum_k A[m][k] * B[o][k]
// CTA tile 128x128, BK=64, 3-stage cp.async pipeline, 8 warps (64x32 each).
// ---------------------------------------------------------------------------
#define GEMM_BK      64
#define A_BYTES      (128 * 128)              // 16 KB
#define STAGE_BYTES  (2 * A_BYTES)            // 32 KB (A + B)
#define SMEM_GEMM    (3 * STAGE_BYTES + 1024) // 99328

__global__ __launch_bounds__(256, 2)
void kan_gemm_mma(const __nv_bfloat16* __restrict__ A,   // [Ntok][Keff]
                  const __nv_bfloat16* __restrict__ B,   // [O][Keff]
                  float* __restrict__ C, int Keff, int ldc) {
    extern __shared__ char smem_raw[];
    const uint32_t sb = (smem_u32(smem_raw) + 1023u) & ~1023u;

    const int tid  = threadIdx.x;
    const int lane = tid & 31;
    const int wid  = tid >> 5;
    const int m0w  = (wid & 1) * 64;    // warp M offset in tile
    const int n0w  = (wid >> 1) * 32;   // warp N offset in tile
    const int m0   = blockIdx.y * 128;
    const int o0   = blockIdx.x * 128;
    const int nch  = Keff / GEMM_BK;

    const __nv_bfloat16* Arow = A + (size_t)m0 * Keff;
    const __nv_bfloat16* Brow = B + (size_t)o0 * Keff;

    // per-thread gmem load coords (4 x 16B for A, 4 for B per stage)
    const int r0 = tid >> 3;           // 0..31 (it adds +32 per step)
    const int c16t = tid & 7;          // 16B column within 128B row

    float acc[4][4][4];
#pragma unroll
    for (int mi = 0; mi < 4; mi++)
#pragma unroll
        for (int nj = 0; nj < 4; nj++)
#pragma unroll
            for (int e = 0; e < 4; e++) acc[mi][nj][e] = 0.0f;

    auto load_chunk = [&](int L, int s) {
        const uint32_t aB = sb + s * STAGE_BYTES;
        const uint32_t bB = aB + A_BYTES;
        const __nv_bfloat16* Ap = Arow + (size_t)L * GEMM_BK + c16t * 8;
        const __nv_bfloat16* Bp = Brow + (size_t)L * GEMM_BK + c16t * 8;
#pragma unroll
        for (int it = 0; it < 4; it++) {
            int row = r0 + it * 32;
            CP_ASYNC16(lds_addr(aB, row, c16t), Ap + (size_t)row * Keff);
        }
#pragma unroll
        for (int it = 0; it < 4; it++) {
            int row = r0 + it * 32;
            CP_ASYNC16(lds_addr(bB, row, c16t), Bp + (size_t)row * Keff);
        }
    };

    // prologue: stages 0 and 1
    load_chunk(0, 0); CP_COMMIT();
    load_chunk(1, 1); CP_COMMIT();

    for (int c = 0; c < nch; c++) {
        CP_WAIT1();                 // chunk c resident
        __syncthreads();            // visible to all; prev compute done
        if (c + 2 < nch) load_chunk(c + 2, (c + 2) % 3);
        CP_COMMIT();                // (possibly empty) keeps group count uniform

        const uint32_t aB = sb + (c % 3) * STAGE_BYTES;
        const uint32_t bB = aB + A_BYTES;
#pragma unroll
        for (int kk = 0; kk < 4; kk++) {
            uint32_t a[4][4];
#pragma unroll
            for (int mi = 0; mi < 4; mi++)
                ldsm_x4(a[mi], lds_addr(aB, m0w + mi * 16 + (lane & 15),
                                        kk * 2 + (lane >> 4)));
            uint32_t b[2][4];
#pragma unroll
            for (int nj2 = 0; nj2 < 2; nj2++) {
                int rowB = n0w + nj2 * 16 + ((lane >> 4) << 3) + (lane & 7);
                int colB = kk * 2 + ((lane >> 3) & 1);
                ldsm_x4(b[nj2], lds_addr(bB, rowB, colB));
            }
#pragma unroll
            for (int mi = 0; mi < 4; mi++)
#pragma unroll
                for (int nj = 0; nj < 4; nj++)
                    mma16816(acc[mi][nj], a[mi], &b[nj >> 1][(nj & 1) * 2]);
        }
    }

    // epilogue: direct stores (fragment: c0,c1 row g cols t*2; c2,c3 row g+8)
    const int g = lane >> 2;
    const int cc0 = (lane & 3) * 2;
#pragma unroll
    for (int mi = 0; mi < 4; mi++) {
#pragma unroll
        for (int nj = 0; nj < 4; nj++) {
            int row = m0 + m0w + mi * 16 + g;
            int col = o0 + n0w + nj * 8 + cc0;
            float2 v0 = make_float2(acc[mi][nj][0], acc[mi][nj][1]);
            float2 v1 = make_float2(acc[mi][nj][2], acc[mi][nj][3]);
            *reinterpret_cast<float2*>(&C[(size_t)row * ldc + col]) = v0;
            *reinterpret_cast<float2*>(&C[(size_t)(row + 8) * ldc + col]) = v1;
        }
    }
}

// ---------------------------------------------------------------------------
// Launch
// ---------------------------------------------------------------------------
extern "C" void kernel_launch(void* const* d_in, const int* in_sizes, int n_in,
                              void* d_out, int out_size) {
    const float* x   = (const float*)d_in[0];
    const float* c1  = (const float*)d_in[1];
    const float* sb1 = (const float*)d_in[2];
    const float* sp1 = (const float*)d_in[3];
    const float* c2  = (const float*)d_in[4];
    const float* sb2 = (const float*)d_in[5];
    const float* sp2 = (const float*)d_in[6];
    float* out = (float*)d_out;

    const int D = D_MODEL, H = HIDDEN;
    const int N = in_sizes[0] / D;   // 4096

    void *pF, *pW1, *pW2, *pH;
    cudaGetSymbolAddress(&pF,  g_F);
    cudaGetSymbolAddress(&pW1, g_W1);
    cudaGetSymbolAddress(&pW2, g_W2);
    cudaGetSymbolAddress(&pH,  g_h);
    __nv_bfloat16* Fq  = (__nv_bfloat16*)pF;
    __nv_bfloat16* W1q = (__nv_bfloat16*)pW1;
    __nv_bfloat16* W2q = (__nv_bfloat16*)pW2;
    float* hb = (float*)pH;

    cudaFuncSetAttribute(kan_gemm_mma,
                         cudaFuncAttributeMaxDynamicSharedMemorySize, SMEM_GEMM);

    // Fold + quantize weights
    prep_weights_q<<<(D * H + 255) / 256, 256>>>(c1, sb1, sp1, W1q, D, H);
    prep_weights_q<<<(H * D + 255) / 256, 256>>>(c2, sb2, sp2, W2q, H, D);

    // Layer 1: features + GEMM (Keff = 13824, O = 1024)
    build_features_q<<<(N * D + 255) / 256, 256>>>(x, Fq, D, N);
    kan_gemm_mma<<<dim3(H / 128, N / 128), 256, SMEM_GEMM>>>(Fq, W1q, hb, KEFF1, H);

    // Layer 2: features + GEMM (Keff = 27648, O = 512)
    build_features_q<<<(N * H + 255) / 256, 256>>>(hb, Fq, H, N);
    kan_gemm_mma<<<dim3(D / 128, N / 128), 256, SMEM_GEMM>>>(Fq, W2q, out, KEFF2, D);
}

// round 6
// speedup vs baseline: 2.1547x; 1.2031x over previous
#include <cuda_runtime.h>
#include <cuda_bf16.h>
#include <math.h>
#include <stdint.h>

// ---------------------------------------------------------------------------
// KAN feedforward via mma.sync bf16 with 3-term precision split.
//   Logical A' = [Fhi | Fhi | Flo], B' = [Whi | Wlo | Whi]  (Keff = 3K)
//   Stored physically deduped: F = [Fhi | Flo], W = [Whi | Wlo]  (2K wide),
//   remapped per k-chunk inside the GEMM.
// GEMM: CTA 128x128, 4 warps of 64x64, BK=64, 3-stage cp.async,
//       register double-buffered fragments. Split-K=2 for layer 2.
// ---------------------------------------------------------------------------

#define D_MODEL 512
#define HIDDEN  1024
#define NFEAT   9
#define NTOK    4096
#define K1      (D_MODEL * NFEAT)   // 4608
#define K2      (HIDDEN  * NFEAT)   // 9216

__device__ __nv_bfloat16 g_F  [(size_t)NTOK * 2 * K2];      // 151 MB (per-layer reuse)
__device__ __nv_bfloat16 g_W1 [(size_t)HIDDEN * 2 * K1];    // 18.9 MB
__device__ __nv_bfloat16 g_W2 [(size_t)D_MODEL * 2 * K2];   // 18.9 MB
__device__ float         g_h  [(size_t)NTOK * HIDDEN];      // 16 MB (h, then split-K slabs)

// ---------------------------------------------------------------------------
// Helpers
// ---------------------------------------------------------------------------
__device__ __forceinline__ uint32_t smem_u32(const void* p) {
    uint32_t a;
    asm("{ .reg .u64 t; cvta.to.shared.u64 t, %1; cvt.u32.u64 %0, t; }"
        : "=r"(a) : "l"(p));
    return a;
}

// 128B-row swizzle (8 x 16B units, 1024B atoms); base must be 1024B aligned.
__device__ __forceinline__ uint32_t lds_addr(uint32_t base, int row, int col16) {
    return base + row * 128 + ((col16 ^ (row & 7)) << 4);
}

#define CP_ASYNC16(sm, gm)                                                    \
    asm volatile("cp.async.cg.shared.global [%0], [%1], 16;"                  \
                 :: "r"(sm), "l"(gm) : "memory")
#define CP_COMMIT()  asm volatile("cp.async.commit_group;" ::: "memory")
#define CP_WAIT1()   asm volatile("cp.async.wait_group 1;" ::: "memory")

__device__ __forceinline__ void ldsm_x4(uint32_t r[4], uint32_t addr) {
    asm volatile("ldmatrix.sync.aligned.m8n8.x4.shared.b16 {%0,%1,%2,%3}, [%4];"
                 : "=r"(r[0]), "=r"(r[1]), "=r"(r[2]), "=r"(r[3]) : "r"(addr));
}

__device__ __forceinline__ void mma16816(float c[4], const uint32_t a[4],
                                         const uint32_t b[2]) {
    asm volatile(
        "mma.sync.aligned.m16n8k16.row.col.f32.bf16.bf16.f32 "
        "{%0,%1,%2,%3}, {%4,%5,%6,%7}, {%8,%9}, {%0,%1,%2,%3};"
        : "+f"(c[0]), "+f"(c[1]), "+f"(c[2]), "+f"(c[3])
        : "r"(a[0]), "r"(a[1]), "r"(a[2]), "r"(a[3]), "r"(b[0]), "r"(b[1]));
}

// ---------------------------------------------------------------------------
// Spline features (validated R3/R5)
// ---------------------------------------------------------------------------
__device__ __forceinline__ float knotf(int k) {
    return __fadd_rn(__fmul_rn((float)(k - 3), 0.4f), -1.0f);
}

__device__ __forceinline__ void kan_features(float x, float f[NFEAT]) {
    float sig = 1.0f / (1.0f + expf(-x));
    f[0] = x * sig;
#pragma unroll
    for (int g = 0; g < 8; g++) f[1 + g] = 0.0f;

    float u = (x - knotf(0)) * 2.5f;
    if (u > 16.0f) u = 16.0f;
    if (u < -16.0f) u = -16.0f;
    int j = (int)floorf(u);
    if (j < -1) j = -1;
    if (j > 11) j = 11;
    if (x < knotf(j))            j -= 1;
    else if (x >= knotf(j + 1))  j += 1;
    if (j < 0 || j > 10) return;

    float s  = (x - knotf(j)) * 2.5f;
    float s2 = s * s, s3 = s2 * s;
    float om = 1.0f - s;
    float w0 = om * om * om * (1.0f / 6.0f);
    float w1 = (3.0f * s3 - 6.0f * s2 + 4.0f) * (1.0f / 6.0f);
    float w2 = (-3.0f * s3 + 3.0f * s2 + 3.0f * s + 1.0f) * (1.0f / 6.0f);
    float w3 = s3 * (1.0f / 6.0f);
    float w[4] = {w0, w1, w2, w3};
    int g0 = j - 3;
#pragma unroll
    for (int r = 0; r < 4; r++) {
        int g = g0 + r;
        if (g >= 0 && g < 8) f[1 + g] = w[r];
    }
}

// ---------------------------------------------------------------------------
// Weight fold + quantize:  Wq[o][2K] = [Whi | Wlo]
// ---------------------------------------------------------------------------
__global__ void prep_weights_q(const float* __restrict__ coef,
                               const float* __restrict__ sbase,
                               const float* __restrict__ ssp,
                               __nv_bfloat16* __restrict__ Wq, int I, int O) {
    int idx = blockIdx.x * blockDim.x + threadIdx.x;
    if (idx >= I * O) return;
    int o = idx / I;
    int i = idx - o * I;
    int K = I * NFEAT;
    size_t io = (size_t)i * O + o;
    float sp = ssp[io];
    float w[NFEAT];
    w[0] = sbase[io];
    const float* c = coef + io * 8;
#pragma unroll
    for (int g = 0; g < 8; g++) w[1 + g] = c[g] * sp;

    size_t base = (size_t)o * 2 * K + (size_t)i * NFEAT;
#pragma unroll
    for (int fi = 0; fi < NFEAT; fi++) {
        __nv_bfloat16 h = __float2bfloat16(w[fi]);
        Wq[base + fi] = h;
        Wq[base + (size_t)K + fi] = __float2bfloat16(w[fi] - __bfloat162float(h));
    }
}

// ---------------------------------------------------------------------------
// Feature expand + quantize:  Fq[n][2K] = [Fhi | Flo]
// ---------------------------------------------------------------------------
__global__ void build_features_q(const float* __restrict__ X,
                                 __nv_bfloat16* __restrict__ Fq, int I, int N) {
    int idx = blockIdx.x * blockDim.x + threadIdx.x;
    if (idx >= N * I) return;
    int n = idx / I;
    int i = idx - n * I;
    int K = I * NFEAT;
    float f[NFEAT];
    kan_features(X[idx], f);
    size_t base = (size_t)n * 2 * K + (size_t)i * NFEAT;
#pragma unroll
    for (int fi = 0; fi < NFEAT; fi++) {
        __nv_bfloat16 h = __float2bfloat16(f[fi]);
        Fq[base + fi] = h;
        Fq[base + (size_t)K + fi] = __float2bfloat16(f[fi] - __bfloat162float(h));
    }
}

// ---------------------------------------------------------------------------
// GEMM:  C[m][o] = sum over logical chunks of A'[m][.] * B'[o][.]
// A phys [Ntok][2K]: logical chunk c -> phys (c<nK ? c : c-nK)
// B phys [O][2K]:    logical chunk c -> phys (c<2nK ? c : c-2nK)
// CTA 128x128, 4 warps 64x64, BK=64, 3 stages, split-K via blockIdx.z.
// ---------------------------------------------------------------------------
#define GEMM_BK      64
#define A_BYTES      (128 * 128)              // 16 KB per stage side
#define STAGE_BYTES  (2 * A_BYTES)            // 32 KB
#define SMEM_GEMM    (3 * STAGE_BYTES)        // 96 KB

__global__ __launch_bounds__(128, 2)
void kan_gemm_mma(const __nv_bfloat16* __restrict__ A,
                  const __nv_bfloat16* __restrict__ B,
                  float* __restrict__ C,
                  int nK, int nchunks, int PK, int ldc, size_t csplit) {
    extern __shared__ __align__(1024) char smem_raw[];
    const uint32_t sb = smem_u32(smem_raw);

    const int tid  = threadIdx.x;
    const int lane = tid & 31;
    const int wid  = tid >> 5;
    const int m0w  = (wid & 1) * 64;
    const int n0w  = (wid >> 1) * 64;
    const int m0   = blockIdx.y * 128;
    const int o0   = blockIdx.x * 128;
    const int z0   = blockIdx.z * nchunks;
    float* Cz      = C + (size_t)blockIdx.z * csplit;

    const __nv_bfloat16* Arow = A + (size_t)m0 * PK;
    const __nv_bfloat16* Brow = B + (size_t)o0 * PK;

    const int r0   = tid >> 3;          // 0..15, +16 per iter
    const int c16t = tid & 7;

    float acc[4][8][4];
#pragma unroll
    for (int mi = 0; mi < 4; mi++)
#pragma unroll
        for (int nj = 0; nj < 8; nj++)
#pragma unroll
            for (int e = 0; e < 4; e++) acc[mi][nj][e] = 0.0f;

    auto a_chunk = [&](int c) -> const __nv_bfloat16* {
        int p = (c < nK) ? c : c - nK;
        return Arow + (size_t)p * GEMM_BK;
    };
    auto b_chunk = [&](int c) -> const __nv_bfloat16* {
        int p = (c < 2 * nK) ? c : c - 2 * nK;
        return Brow + (size_t)p * GEMM_BK;
    };

    auto load_chunk = [&](int logical_c, int s) {
        const uint32_t aB = sb + s * STAGE_BYTES;
        const uint32_t bB = aB + A_BYTES;
        const __nv_bfloat16* Ap = a_chunk(logical_c) + c16t * 8;
        const __nv_bfloat16* Bp = b_chunk(logical_c) + c16t * 8;
#pragma unroll
        for (int it = 0; it < 8; it++) {
            int row = r0 + it * 16;
            CP_ASYNC16(lds_addr(aB, row, c16t), Ap + (size_t)row * PK);
        }
#pragma unroll
        for (int it = 0; it < 8; it++) {
            int row = r0 + it * 16;
            CP_ASYNC16(lds_addr(bB, row, c16t), Bp + (size_t)row * PK);
        }
    };

    // fragment loaders (double-buffered)
    uint32_t fa[2][4][4], fb[2][4][4];
    auto load_frags = [&](uint32_t aB, uint32_t bB, int kk, int buf) {
#pragma unroll
        for (int mi = 0; mi < 4; mi++)
            ldsm_x4(fa[buf][mi], lds_addr(aB, m0w + mi * 16 + (lane & 15),
                                          kk * 2 + (lane >> 4)));
#pragma unroll
        for (int nj2 = 0; nj2 < 4; nj2++) {
            int rowB = n0w + nj2 * 16 + ((lane >> 4) << 3) + (lane & 7);
            int colB = kk * 2 + ((lane >> 3) & 1);
            ldsm_x4(fb[buf][nj2], lds_addr(bB, rowB, colB));
        }
    };

    // prologue: stages 0 and 1
    load_chunk(z0 + 0, 0); CP_COMMIT();
    load_chunk(z0 + 1, 1); CP_COMMIT();

    for (int cc = 0; cc < nchunks; cc++) {
        CP_WAIT1();
        __syncthreads();
        if (cc + 2 < nchunks) load_chunk(z0 + cc + 2, (cc + 2) % 3);
        CP_COMMIT();

        const uint32_t aB = sb + (cc % 3) * STAGE_BYTES;
        const uint32_t bB = aB + A_BYTES;
        load_frags(aB, bB, 0, 0);
#pragma unroll
        for (int kk = 0; kk < 4; kk++) {
            const int cur = kk & 1;
            if (kk < 3) load_frags(aB, bB, kk + 1, cur ^ 1);
#pragma unroll
            for (int mi = 0; mi < 4; mi++)
#pragma unroll
                for (int nj = 0; nj < 8; nj++)
                    mma16816(acc[mi][nj], fa[cur][mi], &fb[cur][nj >> 1][(nj & 1) * 2]);
        }
    }

    // epilogue: direct float2 stores
    const int g   = lane >> 2;
    const int cc0 = (lane & 3) * 2;
#pragma unroll
    for (int mi = 0; mi < 4; mi++) {
#pragma unroll
        for (int nj = 0; nj < 8; nj++) {
            int row = m0 + m0w + mi * 16 + g;
            int col = o0 + n0w + nj * 8 + cc0;
            float2 v0 = make_float2(acc[mi][nj][0], acc[mi][nj][1]);
            float2 v1 = make_float2(acc[mi][nj][2], acc[mi][nj][3]);
            *reinterpret_cast<float2*>(&Cz[(size_t)row * ldc + col]) = v0;
            *reinterpret_cast<float2*>(&Cz[(size_t)(row + 8) * ldc + col]) = v1;
        }
    }
}

// ---------------------------------------------------------------------------
// Split-K reduction: out = s0 + s1  (n floats, float4 granularity)
// ---------------------------------------------------------------------------
__global__ void add_splits(const float* __restrict__ s, float* __restrict__ out,
                           int n4) {
    int i = blockIdx.x * blockDim.x + threadIdx.x;
    if (i >= n4) return;
    float4 a = reinterpret_cast<const float4*>(s)[i];
    float4 b = reinterpret_cast<const float4*>(s)[i + n4];
    out[i * 4 + 0] = a.x + b.x;
    out[i * 4 + 1] = a.y + b.y;
    out[i * 4 + 2] = a.z + b.z;
    out[i * 4 + 3] = a.w + b.w;
}

// ---------------------------------------------------------------------------
// Launch
// ---------------------------------------------------------------------------
extern "C" void kernel_launch(void* const* d_in, const int* in_sizes, int n_in,
                              void* d_out, int out_size) {
    const float* x   = (const float*)d_in[0];
    const float* c1  = (const float*)d_in[1];
    const float* sb1 = (const float*)d_in[2];
    const float* sp1 = (const float*)d_in[3];
    const float* c2  = (const float*)d_in[4];
    const float* sb2 = (const float*)d_in[5];
    const float* sp2 = (const float*)d_in[6];
    float* out = (float*)d_out;

    const int D = D_MODEL, H = HIDDEN;
    const int N = in_sizes[0] / D;   // 4096

    void *pF, *pW1, *pW2, *pH;
    cudaGetSymbolAddress(&pF,  g_F);
    cudaGetSymbolAddress(&pW1, g_W1);
    cudaGetSymbolAddress(&pW2, g_W2);
    cudaGetSymbolAddress(&pH,  g_h);
    __nv_bfloat16* Fq  = (__nv_bfloat16*)pF;
    __nv_bfloat16* W1q = (__nv_bfloat16*)pW1;
    __nv_bfloat16* W2q = (__nv_bfloat16*)pW2;
    float* hb = (float*)pH;

    static bool attr_set = false;
    if (!attr_set) {
        cudaFuncSetAttribute(kan_gemm_mma,
                             cudaFuncAttributeMaxDynamicSharedMemorySize, SMEM_GEMM);
        attr_set = true;
    }

    // Fold + quantize weights  (phys [Whi | Wlo])
    prep_weights_q<<<(D * H + 255) / 256, 256>>>(c1, sb1, sp1, W1q, D, H);
    prep_weights_q<<<(H * D + 255) / 256, 256>>>(c2, sb2, sp2, W2q, H, D);

    // Layer 1: nK = K1/64 = 72, logical chunks = 216, no split
    build_features_q<<<(N * D + 255) / 256, 256>>>(x, Fq, D, N);
    kan_gemm_mma<<<dim3(H / 128, N / 128, 1), 128, SMEM_GEMM>>>(
        Fq, W1q, hb, K1 / 64, 3 * (K1 / 64), 2 * K1, H, 0);

    // Layer 2: nK = K2/64 = 144, logical chunks = 432, split-K = 2 (216 each)
    build_features_q<<<(N * H + 255) / 256, 256>>>(hb, Fq, H, N);
    // hb is dead now; reuse g_h as two split slabs of N*D floats each
    kan_gemm_mma<<<dim3(D / 128, N / 128, 2), 128, SMEM_GEMM>>>(
        Fq, W2q, hb, K2 / 64, (3 * (K2 / 64)) / 2, 2 * K2, D,
        (size_t)N * D);

    add_splits<<<(N * D / 4 + 255) / 256, 256>>>(hb, out, N * D / 4);
}

// round 7
// speedup vs baseline: 3.0021x; 1.3933x over previous
#include <cuda_runtime.h>
#include <cuda_bf16.h>
#include <math.h>
#include <stdint.h>

// ---------------------------------------------------------------------------
// KAN feedforward via mma.sync bf16 with 3-term precision split.
//   Logical A' = [Fhi | Fhi | Flo], B' = [Whi | Wlo | Whi]  (Keff = 3K)
//   Stored deduped: F = [Fhi | Flo], W = [Whi | Wlo] (2K), remapped per chunk.
// R7: coalesced (smem-staged) feature/weight quantization kernels.
// ---------------------------------------------------------------------------

#define D_MODEL 512
#define HIDDEN  1024
#define NFEAT   9
#define NTOK    4096
#define K1      (D_MODEL * NFEAT)   // 4608
#define K2      (HIDDEN  * NFEAT)   // 9216

__device__ __nv_bfloat16 g_F  [(size_t)NTOK * 2 * K2];      // 151 MB
__device__ __nv_bfloat16 g_W1 [(size_t)HIDDEN * 2 * K1];    // 18.9 MB
__device__ __nv_bfloat16 g_W2 [(size_t)D_MODEL * 2 * K2];   // 18.9 MB
__device__ float         g_h  [(size_t)NTOK * HIDDEN];      // 16 MB

// ---------------------------------------------------------------------------
// Helpers
// ---------------------------------------------------------------------------
__device__ __forceinline__ uint32_t smem_u32(const void* p) {
    uint32_t a;
    asm("{ .reg .u64 t; cvta.to.shared.u64 t, %1; cvt.u32.u64 %0, t; }"
        : "=r"(a) : "l"(p));
    return a;
}

__device__ __forceinline__ uint32_t lds_addr(uint32_t base, int row, int col16) {
    return base + row * 128 + ((col16 ^ (row & 7)) << 4);
}

#define CP_ASYNC16(sm, gm)                                                    \
    asm volatile("cp.async.cg.shared.global [%0], [%1], 16;"                  \
                 :: "r"(sm), "l"(gm) : "memory")
#define CP_COMMIT()  asm volatile("cp.async.commit_group;" ::: "memory")
#define CP_WAIT1()   asm volatile("cp.async.wait_group 1;" ::: "memory")

__device__ __forceinline__ void ldsm_x4(uint32_t r[4], uint32_t addr) {
    asm volatile("ldmatrix.sync.aligned.m8n8.x4.shared.b16 {%0,%1,%2,%3}, [%4];"
                 : "=r"(r[0]), "=r"(r[1]), "=r"(r[2]), "=r"(r[3]) : "r"(addr));
}

__device__ __forceinline__ void mma16816(float c[4], const uint32_t a[4],
                                         const uint32_t b[2]) {
    asm volatile(
        "mma.sync.aligned.m16n8k16.row.col.f32.bf16.bf16.f32 "
        "{%0,%1,%2,%3}, {%4,%5,%6,%7}, {%8,%9}, {%0,%1,%2,%3};"
        : "+f"(c[0]), "+f"(c[1]), "+f"(c[2]), "+f"(c[3])
        : "r"(a[0]), "r"(a[1]), "r"(a[2]), "r"(a[3]), "r"(b[0]), "r"(b[1]));
}

// ---------------------------------------------------------------------------
// Spline features (validated R3/R5/R6)
// ---------------------------------------------------------------------------
__device__ __forceinline__ float knotf(int k) {
    return __fadd_rn(__fmul_rn((float)(k - 3), 0.4f), -1.0f);
}

__device__ __forceinline__ void kan_features(float x, float f[NFEAT]) {
    float sig = 1.0f / (1.0f + expf(-x));
    f[0] = x * sig;
#pragma unroll
    for (int g = 0; g < 8; g++) f[1 + g] = 0.0f;

    float u = (x - knotf(0)) * 2.5f;
    if (u > 16.0f) u = 16.0f;
    if (u < -16.0f) u = -16.0f;
    int j = (int)floorf(u);
    if (j < -1) j = -1;
    if (j > 11) j = 11;
    if (x < knotf(j))            j -= 1;
    else if (x >= knotf(j + 1))  j += 1;
    if (j < 0 || j > 10) return;

    float s  = (x - knotf(j)) * 2.5f;
    float s2 = s * s, s3 = s2 * s;
    float om = 1.0f - s;
    float w0 = om * om * om * (1.0f / 6.0f);
    float w1 = (3.0f * s3 - 6.0f * s2 + 4.0f) * (1.0f / 6.0f);
    float w2 = (-3.0f * s3 + 3.0f * s2 + 3.0f * s + 1.0f) * (1.0f / 6.0f);
    float w3 = s3 * (1.0f / 6.0f);
    float w[4] = {w0, w1, w2, w3};
    int g0 = j - 3;
#pragma unroll
    for (int r = 0; r < 4; r++) {
        int g = g0 + r;
        if (g >= 0 && g < 8) f[1 + g] = w[r];
    }
}

// ---------------------------------------------------------------------------
// Coalesced feature expand + quantize.
// Block = 256 threads, handles (n = blockIdx.x, i in [i0, i0+256)).
// Stage hi/lo bf16 in smem, then cooperative coalesced uint32 copy-out.
//   Fq[n][2K] = [Fhi | Flo],  hi run at n*2K + i0*9, length 2304 elems.
// ---------------------------------------------------------------------------
__global__ __launch_bounds__(256)
void build_features_q(const float* __restrict__ X,
                      __nv_bfloat16* __restrict__ Fq, int I) {
    __shared__ __align__(16) __nv_bfloat16 sh[256 * NFEAT];
    __shared__ __align__(16) __nv_bfloat16 sl[256 * NFEAT];
    const int n  = blockIdx.x;
    const int i0 = blockIdx.y << 8;
    const int t  = threadIdx.x;
    const int K  = I * NFEAT;

    float x = X[(size_t)n * I + i0 + t];
    float f[NFEAT];
    kan_features(x, f);
#pragma unroll
    for (int fi = 0; fi < NFEAT; fi++) {
        __nv_bfloat16 h = __float2bfloat16(f[fi]);
        sh[t * NFEAT + fi] = h;
        sl[t * NFEAT + fi] = __float2bfloat16(f[fi] - __bfloat162float(h));
    }
    __syncthreads();

    const uint32_t* s32h = reinterpret_cast<const uint32_t*>(sh);
    const uint32_t* s32l = reinterpret_cast<const uint32_t*>(sl);
    size_t base = (size_t)n * 2 * K + (size_t)i0 * NFEAT;
    uint32_t* dh = reinterpret_cast<uint32_t*>(Fq + base);
    uint32_t* dl = reinterpret_cast<uint32_t*>(Fq + base + K);
    // 256*9 bf16 = 1152 uint32 per buffer
    for (int p = t; p < 1152; p += 256) {
        dh[p] = s32h[p];
        dl[p] = s32l[p];
    }
}

// ---------------------------------------------------------------------------
// Coalesced weight fold + quantize.
// Block = 256 threads, handles (o = blockIdx.x, i in [i0, i0+256)).
//   Wq[o][2K] = [Whi | Wlo]
// coef reads: 32B/thread (one sector) — already ideal. Writes staged.
// ---------------------------------------------------------------------------
__global__ __launch_bounds__(256)
void prep_weights_q(const float* __restrict__ coef,
                    const float* __restrict__ sbase,
                    const float* __restrict__ ssp,
                    __nv_bfloat16* __restrict__ Wq, int I, int O) {
    __shared__ __align__(16) __nv_bfloat16 sh[256 * NFEAT];
    __shared__ __align__(16) __nv_bfloat16 sl[256 * NFEAT];
    const int o  = blockIdx.x;
    const int i0 = blockIdx.y << 8;
    const int t  = threadIdx.x;
    const int K  = I * NFEAT;
    const int i  = i0 + t;

    size_t io = (size_t)i * O + o;
    float sp = ssp[io];
    float w[NFEAT];
    w[0] = sbase[io];
    const float* c = coef + io * 8;
#pragma unroll
    for (int g = 0; g < 8; g++) w[1 + g] = c[g] * sp;

#pragma unroll
    for (int fi = 0; fi < NFEAT; fi++) {
        __nv_bfloat16 h = __float2bfloat16(w[fi]);
        sh[t * NFEAT + fi] = h;
        sl[t * NFEAT + fi] = __float2bfloat16(w[fi] - __bfloat162float(h));
    }
    __syncthreads();

    const uint32_t* s32h = reinterpret_cast<const uint32_t*>(sh);
    const uint32_t* s32l = reinterpret_cast<const uint32_t*>(sl);
    size_t base = (size_t)o * 2 * K + (size_t)i0 * NFEAT;
    uint32_t* dh = reinterpret_cast<uint32_t*>(Wq + base);
    uint32_t* dl = reinterpret_cast<uint32_t*>(Wq + base + K);
    for (int p = t; p < 1152; p += 256) {
        dh[p] = s32h[p];
        dl[p] = s32l[p];
    }
}

// ---------------------------------------------------------------------------
// GEMM (unchanged from R6 — at ~85% of legacy-HMMA ceiling):
// CTA 128x128, 4 warps 64x64, BK=64, 3-stage cp.async, reg double-buffering,
// dedup chunk remap, split-K via blockIdx.z.
// ---------------------------------------------------------------------------
#define GEMM_BK      64
#define A_BYTES      (128 * 128)
#define STAGE_BYTES  (2 * A_BYTES)
#define SMEM_GEMM    (3 * STAGE_BYTES)

__global__ __launch_bounds__(128, 2)
void kan_gemm_mma(const __nv_bfloat16* __restrict__ A,
                  const __nv_bfloat16* __restrict__ B,
                  float* __restrict__ C,
                  int nK, int nchunks, int PK, int ldc, size_t csplit) {
    extern __shared__ __align__(1024) char smem_raw[];
    const uint32_t sb = smem_u32(smem_raw);

    const int tid  = threadIdx.x;
    const int lane = tid & 31;
    const int wid  = tid >> 5;
    const int m0w  = (wid & 1) * 64;
    const int n0w  = (wid >> 1) * 64;
    const int m0   = blockIdx.y * 128;
    const int o0   = blockIdx.x * 128;
    const int z0   = blockIdx.z * nchunks;
    float* Cz      = C + (size_t)blockIdx.z * csplit;

    const __nv_bfloat16* Arow = A + (size_t)m0 * PK;
    const __nv_bfloat16* Brow = B + (size_t)o0 * PK;

    const int r0   = tid >> 3;
    const int c16t = tid & 7;

    float acc[4][8][4];
#pragma unroll
    for (int mi = 0; mi < 4; mi++)
#pragma unroll
        for (int nj = 0; nj < 8; nj++)
#pragma unroll
            for (int e = 0; e < 4; e++) acc[mi][nj][e] = 0.0f;

    auto a_chunk = [&](int c) -> const __nv_bfloat16* {
        int p = (c < nK) ? c : c - nK;
        return Arow + (size_t)p * GEMM_BK;
    };
    auto b_chunk = [&](int c) -> const __nv_bfloat16* {
        int p = (c < 2 * nK) ? c : c - 2 * nK;
        return Brow + (size_t)p * GEMM_BK;
    };

    auto load_chunk = [&](int logical_c, int s) {
        const uint32_t aB = sb + s * STAGE_BYTES;
        const uint32_t bB = aB + A_BYTES;
        const __nv_bfloat16* Ap = a_chunk(logical_c) + c16t * 8;
        const __nv_bfloat16* Bp = b_chunk(logical_c) + c16t * 8;
#pragma unroll
        for (int it = 0; it < 8; it++) {
            int row = r0 + it * 16;
            CP_ASYNC16(lds_addr(aB, row, c16t), Ap + (size_t)row * PK);
        }
#pragma unroll
        for (int it = 0; it < 8; it++) {
            int row = r0 + it * 16;
            CP_ASYNC16(lds_addr(bB, row, c16t), Bp + (size_t)row * PK);
        }
    };

    uint32_t fa[2][4][4], fb[2][4][4];
    auto load_frags = [&](uint32_t aB, uint32_t bB, int kk, int buf) {
#pragma unroll
        for (int mi = 0; mi < 4; mi++)
            ldsm_x4(fa[buf][mi], lds_addr(aB, m0w + mi * 16 + (lane & 15),
                                          kk * 2 + (lane >> 4)));
#pragma unroll
        for (int nj2 = 0; nj2 < 4; nj2++) {
            int rowB = n0w + nj2 * 16 + ((lane >> 4) << 3) + (lane & 7);
            int colB = kk * 2 + ((lane >> 3) & 1);
            ldsm_x4(fb[buf][nj2], lds_addr(bB, rowB, colB));
        }
    };

    load_chunk(z0 + 0, 0); CP_COMMIT();
    load_chunk(z0 + 1, 1); CP_COMMIT();

    for (int cc = 0; cc < nchunks; cc++) {
        CP_WAIT1();
        __syncthreads();
        if (cc + 2 < nchunks) load_chunk(z0 + cc + 2, (cc + 2) % 3);
        CP_COMMIT();

        const uint32_t aB = sb + (cc % 3) * STAGE_BYTES;
        const uint32_t bB = aB + A_BYTES;
        load_frags(aB, bB, 0, 0);
#pragma unroll
        for (int kk = 0; kk < 4; kk++) {
            const int cur = kk & 1;
            if (kk < 3) load_frags(aB, bB, kk + 1, cur ^ 1);
#pragma unroll
            for (int mi = 0; mi < 4; mi++)
#pragma unroll
                for (int nj = 0; nj < 8; nj++)
                    mma16816(acc[mi][nj], fa[cur][mi], &fb[cur][nj >> 1][(nj & 1) * 2]);
        }
    }

    const int g   = lane >> 2;
    const int cc0 = (lane & 3) * 2;
#pragma unroll
    for (int mi = 0; mi < 4; mi++) {
#pragma unroll
        for (int nj = 0; nj < 8; nj++) {
            int row = m0 + m0w + mi * 16 + g;
            int col = o0 + n0w + nj * 8 + cc0;
            float2 v0 = make_float2(acc[mi][nj][0], acc[mi][nj][1]);
            float2 v1 = make_float2(acc[mi][nj][2], acc[mi][nj][3]);
            *reinterpret_cast<float2*>(&Cz[(size_t)row * ldc + col]) = v0;
            *reinterpret_cast<float2*>(&Cz[(size_t)(row + 8) * ldc + col]) = v1;
        }
    }
}

// ---------------------------------------------------------------------------
// Split-K reduction
// ---------------------------------------------------------------------------
__global__ void add_splits(const float* __restrict__ s, float* __restrict__ out,
                           int n4) {
    int i = blockIdx.x * blockDim.x + threadIdx.x;
    if (i >= n4) return;
    float4 a = reinterpret_cast<const float4*>(s)[i];
    float4 b = reinterpret_cast<const float4*>(s)[i + n4];
    out[i * 4 + 0] = a.x + b.x;
    out[i * 4 + 1] = a.y + b.y;
    out[i * 4 + 2] = a.z + b.z;
    out[i * 4 + 3] = a.w + b.w;
}

// ---------------------------------------------------------------------------
// Launch
// ---------------------------------------------------------------------------
extern "C" void kernel_launch(void* const* d_in, const int* in_sizes, int n_in,
                              void* d_out, int out_size) {
    const float* x   = (const float*)d_in[0];
    const float* c1  = (const float*)d_in[1];
    const float* sb1 = (const float*)d_in[2];
    const float* sp1 = (const float*)d_in[3];
    const float* c2  = (const float*)d_in[4];
    const float* sb2 = (const float*)d_in[5];
    const float* sp2 = (const float*)d_in[6];
    float* out = (float*)d_out;

    const int D = D_MODEL, H = HIDDEN;
    const int N = in_sizes[0] / D;   // 4096

    void *pF, *pW1, *pW2, *pH;
    cudaGetSymbolAddress(&pF,  g_F);
    cudaGetSymbolAddress(&pW1, g_W1);
    cudaGetSymbolAddress(&pW2, g_W2);
    cudaGetSymbolAddress(&pH,  g_h);
    __nv_bfloat16* Fq  = (__nv_bfloat16*)pF;
    __nv_bfloat16* W1q = (__nv_bfloat16*)pW1;
    __nv_bfloat16* W2q = (__nv_bfloat16*)pW2;
    float* hb = (float*)pH;

    static bool attr_set = false;
    if (!attr_set) {
        cudaFuncSetAttribute(kan_gemm_mma,
                             cudaFuncAttributeMaxDynamicSharedMemorySize, SMEM_GEMM);
        attr_set = true;
    }

    // Fold + quantize weights (coalesced, staged)
    prep_weights_q<<<dim3(H, D / 256), 256>>>(c1, sb1, sp1, W1q, D, H);
    prep_weights_q<<<dim3(D, H / 256), 256>>>(c2, sb2, sp2, W2q, H, D);

    // Layer 1
    build_features_q<<<dim3(N, D / 256), 256>>>(x, Fq, D);
    kan_gemm_mma<<<dim3(H / 128, N / 128, 1), 128, SMEM_GEMM>>>(
        Fq, W1q, hb, K1 / 64, 3 * (K1 / 64), 2 * K1, H, 0);

    // Layer 2 (split-K = 2)
    build_features_q<<<dim3(N, H / 256), 256>>>(hb, Fq, H);
    kan_gemm_mma<<<dim3(D / 128, N / 128, 2), 128, SMEM_GEMM>>>(
        Fq, W2q, hb, K2 / 64, (3 * (K2 / 64)) / 2, 2 * K2, D,
        (size_t)N * D);

    add_splits<<<(N * D / 4 + 255) / 256, 256>>>(hb, out, N * D / 4);
}